// round 17
// baseline (speedup 1.0000x reference)
#include <cuda_runtime.h>
#include <cuda_fp16.h>
#include <math.h>

#define N_NODES  100000
#define N_EDGES  3200000
#define N_GRAPHS 256
#define CAP      96        // P(in-degree >= 96) ~ e^-41 per node; multiple of 8
#define NTILE    16        // nodes per warp tile in mma_pool (m16)

#define G2_BLOCKS    1184  // 148 SMs x 8 blocks (32 regs, 256 thr) -> one exact wave
#define BUILD_BLOCKS 1184

// -------- scratch (device globals: zero-initialized at module load) --------
// State contract: every kernel_launch leaves deg/cur zeroed, pooled = -inf bits,
// done = 0 (reset in k_mma_pool epilogue), so graph replays are deterministic.
__device__ int    g_deg[N_NODES];                          // starts 0; deg = this + 1
__device__ int    g_cur[N_NODES];
__device__ float  g_dis[N_NODES];
__device__ __align__(16) int g_csr[N_NODES * CAP];         // padded to 8-mult with N_NODES
__device__ __align__(16) float g_ps[(N_NODES + 1) * 4];    // {d*p, d}; row N_NODES stays 0
__device__ __align__(16) __half g_h1[(N_NODES + 1) * 32];  // h1'; row N_NODES stays 0
__device__ __align__(16) __half g_agg2h[N_NODES * 32];     // layer-2 aggregate, fp16
__device__ float  g_pooled[N_GRAPHS * 64];                 // kept at -inf bits between runs
__device__ int    g_pooled_virgin;                         // 0 on first run
__device__ int    g_done;

__device__ __forceinline__ void red_add_s32(int* p, int v) {
    asm volatile("red.global.add.s32 [%0], %1;" :: "l"(p), "r"(v) : "memory");
}

// -------- build: grid-stride over 4-edge quads; also first-run pooled init --------
__global__ void __launch_bounds__(256) k_build(const int4* __restrict__ row4,
                                               const int4* __restrict__ col4) {
    int t0 = blockIdx.x * blockDim.x + threadIdx.x;
    if (t0 < N_GRAPHS * 64) {
        if (g_pooled_virgin == 0)
            reinterpret_cast<int*>(g_pooled)[t0] = 0xFF800000;
    }
    int stride = gridDim.x * blockDim.x;
    for (int t = t0; t < N_EDGES / 4; t += stride) {
        int4 r = row4[t];
        int4 c = col4[t];
        red_add_s32(&g_deg[r.x], 1);
        red_add_s32(&g_deg[r.y], 1);
        red_add_s32(&g_deg[r.z], 1);
        red_add_s32(&g_deg[r.w], 1);
        int l0 = atomicAdd(&g_cur[c.x], 1);
        int l1 = atomicAdd(&g_cur[c.y], 1);
        int l2 = atomicAdd(&g_cur[c.z], 1);
        int l3 = atomicAdd(&g_cur[c.w], 1);
        if (l0 < CAP) g_csr[c.x * CAP + l0] = r.x;
        if (l1 < CAP) g_csr[c.y * CAP + l1] = r.y;
        if (l2 < CAP) g_csr[c.z * CAP + l2] = r.z;
        if (l3 < CAP) g_csr[c.w * CAP + l3] = r.w;
    }
}

// -------- prep (thread per node): d = rsqrt(deg+1), ps, csr pad to 8-mult --------
__global__ void k_prep(const float* __restrict__ pos) {
    int w = blockIdx.x * blockDim.x + threadIdx.x;
    if (w >= N_NODES) return;
    float d = rsqrtf((float)(g_deg[w] + 1));       // +1: self loop
    g_dis[w] = d;

    int cnt = min(g_cur[w], CAP);
    int padded = (cnt + 7) & ~7;
    for (int j = cnt; j < padded; j++) g_csr[w * CAP + j] = N_NODES;  // dummy

    float p0 = pos[w * 3 + 0], p1 = pos[w * 3 + 1], p2 = pos[w * 3 + 2];
    *reinterpret_cast<float4*>(&g_ps[w * 4]) = make_float4(d * p0, d * p1, d * p2, d);
}

// -------- layer 1: 2 nodes/warp interleaved (MLP=2), branchless dummy loads --------
__global__ void k_gather1(const float* __restrict__ W1, const float* __restrict__ b1) {
    int w = (blockIdx.x * blockDim.x + threadIdx.x) >> 5;
    int lane = threadIdx.x & 31;
    int i0 = w * 2;
    if (i0 >= N_NODES) return;
    int i1 = i0 + 1;
    bool v1 = (i1 < N_NODES);

    int cnt0 = min(g_cur[i0], CAP);
    int cnt1 = v1 ? min(g_cur[i1], CAP) : 0;
    int mx = max(cnt0, cnt1);
    const int* csr0 = &g_csr[i0 * CAP];
    const int* csr1 = &g_csr[i1 * CAP];

    float a0 = 0.f, a1 = 0.f, a2 = 0.f;
    float c0 = 0.f, c1 = 0.f, c2 = 0.f;
    for (int j = lane; j < mx; j += 32) {
        int r0 = (j < cnt0) ? __ldg(&csr0[j]) : N_NODES;
        int r1 = (j < cnt1) ? __ldg(&csr1[j]) : N_NODES;
        float4 p0 = *reinterpret_cast<const float4*>(&g_ps[r0 * 4]);  // dummy row = 0
        float4 p1 = *reinterpret_cast<const float4*>(&g_ps[r1 * 4]);
        a0 += p0.x; a1 += p0.y; a2 += p0.z;
        c0 += p1.x; c1 += p1.y; c2 += p1.z;
    }
#pragma unroll
    for (int s = 16; s > 0; s >>= 1) {
        a0 += __shfl_xor_sync(0xffffffff, a0, s);
        a1 += __shfl_xor_sync(0xffffffff, a1, s);
        a2 += __shfl_xor_sync(0xffffffff, a2, s);
        c0 += __shfl_xor_sync(0xffffffff, c0, s);
        c1 += __shfl_xor_sync(0xffffffff, c1, s);
        c2 += __shfl_xor_sync(0xffffffff, c2, s);
    }

    int o = lane;
    float w0 = __ldg(&W1[o * 3 + 0]);
    float w1v = __ldg(&W1[o * 3 + 1]);
    float w2v = __ldg(&W1[o * 3 + 2]);
    float bo = __ldg(&b1[o]);

    {
        float dc = g_dis[i0];
        float4 psc = *reinterpret_cast<const float4*>(&g_ps[i0 * 4]);
        float x0 = dc * (a0 + psc.x);
        float x1 = dc * (a1 + psc.y);
        float x2 = dc * (a2 + psc.z);
        float acc = bo + x0 * w0 + x1 * w1v + x2 * w2v;
        g_h1[i0 * 32 + o] = __float2half(dc * fmaxf(acc, 0.f));
    }
    if (v1) {
        float dc = g_dis[i1];
        float4 psc = *reinterpret_cast<const float4*>(&g_ps[i1 * 4]);
        float x0 = dc * (c0 + psc.x);
        float x1 = dc * (c1 + psc.y);
        float x2 = dc * (c2 + psc.z);
        float acc = bo + x0 * w0 + x1 * w1v + x2 * w2v;
        g_h1[i1 * 32 + o] = __float2half(dc * fmaxf(acc, 0.f));
    }
}

// -------- layer 2 gather: persistent, 4 lanes/edge (uint4 = 8 feats), 8 edges/warp-iter --------
__global__ void __launch_bounds__(256, 8) k_gather2() {
    int gwarp  = (blockIdx.x * blockDim.x + threadIdx.x) >> 5;
    int nwarps = (gridDim.x * blockDim.x) >> 5;
    int lane = threadIdx.x & 31;
    int grp  = lane >> 2;       // edge slot 0..7
    int q    = lane & 3;        // uint4 slot: features q*8 .. q*8+7

    for (int i = gwarp; i < N_NODES; i += nwarps) {
        int padded = (min(g_cur[i], CAP) + 7) & ~7;
        const int* csr = &g_csr[i * CAP];

        float f0 = 0.f, f1 = 0.f, f2 = 0.f, f3 = 0.f;
        float f4 = 0.f, f5 = 0.f, f6 = 0.f, f7 = 0.f;

        int p = 0;
        for (; p + 16 <= padded; p += 16) {       // 16-edge superchunk: 2 chunks
            __half2 a0 = __float2half2_rn(0.f), a1 = __float2half2_rn(0.f);
            __half2 a2 = __float2half2_rn(0.f), a3 = __float2half2_rn(0.f);
#pragma unroll
            for (int u = 0; u < 2; u++) {
                int r = __ldg(&csr[p + u * 8 + grp]);
                uint4 v = __ldg(reinterpret_cast<const uint4*>(g_h1 + r * 32) + q);
                a0 = __hadd2(a0, *reinterpret_cast<__half2*>(&v.x));
                a1 = __hadd2(a1, *reinterpret_cast<__half2*>(&v.y));
                a2 = __hadd2(a2, *reinterpret_cast<__half2*>(&v.z));
                a3 = __hadd2(a3, *reinterpret_cast<__half2*>(&v.w));
            }
            float2 g0 = __half22float2(a0), g1 = __half22float2(a1);
            float2 g2 = __half22float2(a2), g3 = __half22float2(a3);
            f0 += g0.x; f1 += g0.y; f2 += g1.x; f3 += g1.y;
            f4 += g2.x; f5 += g2.y; f6 += g3.x; f7 += g3.y;
        }
        if (p < padded) {                         // one 8-edge chunk left
            int r = __ldg(&csr[p + grp]);
            uint4 v = __ldg(reinterpret_cast<const uint4*>(g_h1 + r * 32) + q);
            float2 g0 = __half22float2(*reinterpret_cast<__half2*>(&v.x));
            float2 g1 = __half22float2(*reinterpret_cast<__half2*>(&v.y));
            float2 g2 = __half22float2(*reinterpret_cast<__half2*>(&v.z));
            float2 g3 = __half22float2(*reinterpret_cast<__half2*>(&v.w));
            f0 += g0.x; f1 += g0.y; f2 += g1.x; f3 += g1.y;
            f4 += g2.x; f5 += g2.y; f6 += g3.x; f7 += g3.y;
        }

        // reduce across the 8 edge-groups (lanes q, q+4, ..., q+28)
#pragma unroll
        for (int s = 4; s <= 16; s <<= 1) {
            f0 += __shfl_xor_sync(0xffffffff, f0, s);
            f1 += __shfl_xor_sync(0xffffffff, f1, s);
            f2 += __shfl_xor_sync(0xffffffff, f2, s);
            f3 += __shfl_xor_sync(0xffffffff, f3, s);
            f4 += __shfl_xor_sync(0xffffffff, f4, s);
            f5 += __shfl_xor_sync(0xffffffff, f5, s);
            f6 += __shfl_xor_sync(0xffffffff, f6, s);
            f7 += __shfl_xor_sync(0xffffffff, f7, s);
        }

        // self loop AFTER reduction (exactly once per feature)
        {
            uint4 v = __ldg(reinterpret_cast<const uint4*>(g_h1 + i * 32) + q);
            float2 g0 = __half22float2(*reinterpret_cast<__half2*>(&v.x));
            float2 g1 = __half22float2(*reinterpret_cast<__half2*>(&v.y));
            float2 g2 = __half22float2(*reinterpret_cast<__half2*>(&v.z));
            float2 g3 = __half22float2(*reinterpret_cast<__half2*>(&v.w));
            f0 += g0.x; f1 += g0.y; f2 += g1.x; f3 += g1.y;
            f4 += g2.x; f5 += g2.y; f6 += g3.x; f7 += g3.y;
        }

        if (lane < 4) {
            float d = g_dis[i];
            __half2 o0 = __floats2half2_rn(d * f0, d * f1);
            __half2 o1 = __floats2half2_rn(d * f2, d * f3);
            __half2 o2 = __floats2half2_rn(d * f4, d * f5);
            __half2 o3 = __floats2half2_rn(d * f6, d * f7);
            uint4 w;
            w.x = *reinterpret_cast<unsigned*>(&o0);
            w.y = *reinterpret_cast<unsigned*>(&o1);
            w.z = *reinterpret_cast<unsigned*>(&o2);
            w.w = *reinterpret_cast<unsigned*>(&o3);
            *(reinterpret_cast<uint4*>(g_agg2h + i * 32) + q) = w;
        }
    }
}

// -------- transform2 (HMMA) + relu + pool + head + state reset --------
__global__ void __launch_bounds__(256) k_mma_pool(const float* __restrict__ W2,
                                                  const float* __restrict__ b2,
                                                  const int*   __restrict__ batch,
                                                  const float* __restrict__ Wc,
                                                  const float* __restrict__ bc,
                                                  float*       __restrict__ out) {
    __shared__ __align__(16) __half sA[8 * 16 * 40];
    __shared__ __align__(16) __half sW2[32 * 72];

    int tid = threadIdx.x;
    int wid = tid >> 5;
    int lane = tid & 31;

    for (int x = tid; x < 32 * 64; x += 256) {
        int k = x >> 6, o = x & 63;
        sW2[k * 72 + o] = __float2half(__ldg(&W2[o * 32 + k]));
    }
    __syncthreads();

    int warp = blockIdx.x * 8 + wid;
    int base = warp * NTILE;

    if (base < N_NODES) {
        __half* Aw = &sA[wid * 16 * 40];
        const uint4* src = reinterpret_cast<const uint4*>(g_agg2h) + base * 4;
#pragma unroll
        for (int k = 0; k < 2; k++) {
            int c = lane + 32 * k;
            uint4 v = __ldg(&src[c]);
            *reinterpret_cast<uint4*>(reinterpret_cast<char*>(Aw) + (c >> 2) * 80 + (c & 3) * 16) = v;
        }
        __syncwarp();

        unsigned a0[4], a1[4];
        {
            unsigned ab = (unsigned)__cvta_generic_to_shared(Aw);
            unsigned addr0 = ab + (lane & 15) * 80 + (lane >> 4) * 16;
            asm volatile("ldmatrix.sync.aligned.m8n8.x4.shared.b16 {%0,%1,%2,%3}, [%4];"
                         : "=r"(a0[0]), "=r"(a0[1]), "=r"(a0[2]), "=r"(a0[3]) : "r"(addr0));
            unsigned addr1 = addr0 + 32;
            asm volatile("ldmatrix.sync.aligned.m8n8.x4.shared.b16 {%0,%1,%2,%3}, [%4];"
                         : "=r"(a1[0]), "=r"(a1[1]), "=r"(a1[2]), "=r"(a1[3]) : "r"(addr1));
        }

        float c[8][4];
#pragma unroll
        for (int n0 = 0; n0 < 8; n0++) { c[n0][0] = c[n0][1] = c[n0][2] = c[n0][3] = 0.f; }

        unsigned wb = (unsigned)__cvta_generic_to_shared(sW2);
#pragma unroll
        for (int n0 = 0; n0 < 8; n0++) {
            unsigned b0, b1;
            unsigned baddr0 = wb + (lane & 15) * 144 + n0 * 16;
            asm volatile("ldmatrix.sync.aligned.m8n8.x2.trans.shared.b16 {%0,%1}, [%2];"
                         : "=r"(b0), "=r"(b1) : "r"(baddr0));
            asm volatile("mma.sync.aligned.m16n8k16.row.col.f32.f16.f16.f32 "
                         "{%0,%1,%2,%3}, {%4,%5,%6,%7}, {%8,%9}, {%0,%1,%2,%3};"
                         : "+f"(c[n0][0]), "+f"(c[n0][1]), "+f"(c[n0][2]), "+f"(c[n0][3])
                         : "r"(a0[0]), "r"(a0[1]), "r"(a0[2]), "r"(a0[3]), "r"(b0), "r"(b1));
            unsigned baddr1 = wb + (16 + (lane & 15)) * 144 + n0 * 16;
            asm volatile("ldmatrix.sync.aligned.m8n8.x2.trans.shared.b16 {%0,%1}, [%2];"
                         : "=r"(b0), "=r"(b1) : "r"(baddr1));
            asm volatile("mma.sync.aligned.m16n8k16.row.col.f32.f16.f16.f32 "
                         "{%0,%1,%2,%3}, {%4,%5,%6,%7}, {%8,%9}, {%0,%1,%2,%3};"
                         : "+f"(c[n0][0]), "+f"(c[n0][1]), "+f"(c[n0][2]), "+f"(c[n0][3])
                         : "r"(a1[0]), "r"(a1[1]), "r"(a1[2]), "r"(a1[3]), "r"(b0), "r"(b1));
        }

        int q = lane & 3;
#pragma unroll
        for (int n0 = 0; n0 < 8; n0++) {
            float bx = __ldg(&b2[n0 * 8 + q * 2]);
            float by = __ldg(&b2[n0 * 8 + q * 2 + 1]);
            c[n0][0] = fmaxf(c[n0][0] + bx, 0.f);
            c[n0][1] = fmaxf(c[n0][1] + by, 0.f);
            c[n0][2] = fmaxf(c[n0][2] + bx, 0.f);
            c[n0][3] = fmaxf(c[n0][3] + by, 0.f);
        }

        int bA = __ldg(&batch[base + (lane >> 2)]);
        int bB = __ldg(&batch[base + 8 + (lane >> 2)]);
        int gfirst = __ldg(&batch[base]);
        int glast  = __ldg(&batch[base + 15]);

        for (int g = gfirst; g <= glast; g++) {
            bool m0 = (bA == g), m1 = (bB == g);
#pragma unroll
            for (int n0 = 0; n0 < 8; n0++) {
                float v0 = fmaxf(m0 ? c[n0][0] : 0.f, m1 ? c[n0][2] : 0.f);
                float v1 = fmaxf(m0 ? c[n0][1] : 0.f, m1 ? c[n0][3] : 0.f);
#pragma unroll
                for (int s = 4; s <= 16; s <<= 1) {
                    v0 = fmaxf(v0, __shfl_xor_sync(0xffffffff, v0, s));
                    v1 = fmaxf(v1, __shfl_xor_sync(0xffffffff, v1, s));
                }
                if (lane < 4) {
                    atomicMax(reinterpret_cast<int*>(&g_pooled[g * 64 + n0 * 8 + lane * 2]),
                              __float_as_int(v0));
                    atomicMax(reinterpret_cast<int*>(&g_pooled[g * 64 + n0 * 8 + lane * 2 + 1]),
                              __float_as_int(v1));
                }
            }
        }
    }

    // ---- state reset for next launch: deg/cur back to 0 ----
    for (int j = blockIdx.x * 256 + tid; j < N_NODES; j += gridDim.x * 256) {
        g_deg[j] = 0;
        g_cur[j] = 0;
    }

    // ---- last-block head + pooled/done reset ----
    __threadfence();
    __shared__ int sLast;
    if (tid == 0) sLast = (atomicAdd(&g_done, 1) == (int)gridDim.x - 1);
    __syncthreads();
    if (sLast) {
        for (int t = tid; t < N_GRAPHS * 2; t += 256) {
            int g = t >> 1;
            int o = t & 1;
            float acc = __ldg(&bc[o]);
#pragma unroll
            for (int k = 0; k < 64; k++)
                acc = fmaf(__ldcg(&g_pooled[g * 64 + k]), __ldg(&Wc[o * 64 + k]), acc);
            out[t] = acc;
        }
        __syncthreads();                 // head reads complete before reset
        for (int t = tid; t < N_GRAPHS * 64; t += 256)
            reinterpret_cast<int*>(g_pooled)[t] = 0xFF800000;
        if (tid == 0) { g_done = 0; g_pooled_virgin = 1; }
    }
}

extern "C" void kernel_launch(void* const* d_in, const int* in_sizes, int n_in,
                              void* d_out, int out_size) {
    const float* pos  = (const float*)d_in[0];
    const int*   eidx = (const int*)  d_in[1];
    const int*   bat  = (const int*)  d_in[2];
    const float* W1   = (const float*)d_in[3];
    const float* b1   = (const float*)d_in[4];
    const float* W2   = (const float*)d_in[5];
    const float* b2   = (const float*)d_in[6];
    const float* Wc   = (const float*)d_in[7];
    const float* bc   = (const float*)d_in[8];
    float* out = (float*)d_out;

    const int* row = eidx;             // edge_index[0]
    const int* col = eidx + N_EDGES;   // edge_index[1]

    const int TB = 256;

    k_build<<<BUILD_BLOCKS, TB>>>((const int4*)row, (const int4*)col);
    k_prep <<<(N_NODES + TB - 1) / TB, TB>>>(pos);
    {
        int warps = (N_NODES + 1) / 2;                // 2 nodes per warp
        int blocks = (warps * 32 + TB - 1) / TB;
        k_gather1<<<blocks, TB>>>(W1, b1);
    }
    k_gather2<<<G2_BLOCKS, TB>>>();
    {
        int warps = (N_NODES + NTILE - 1) / NTILE;   // 6250
        int blocks = (warps + 7) / 8;                // 782
        k_mma_pool<<<blocks, TB>>>(W2, b2, bat, Wc, bc, out);
    }
}